// round 3
// baseline (speedup 1.0000x reference)
#include <cuda_runtime.h>
#include <cuda_bf16.h>
#include <cstdint>

// MaxUnpooling2D: scatter-add updates into a zeroed output.
//   updates: f32 [8,128,128,256]  = 33,554,432 elems (134 MB)
//   mask:    i32 same shape, values in [0, 2^24)
//   out:     f32 [8,256,256,256]  = 134,217,728 elems (536 MB)
//   flat index = mask[i] + batch * 4,194,304 (batch offset uses INPUT size, per ref)
// Per-batch input size = 2^22 elems, so batch = elem_index >> 22, and a
// float4 thread's 4 consecutive elems always share one batch (4 | 2^22).

static constexpr int N_UPD  = 33554432;    // updates / mask elems (8 * 2^22)
static constexpr int N_OUT  = 134217728;   // output elems (8 * 2^24)
static constexpr int BATCH_SHIFT = 22;     // flat_input_size = 2^22

__global__ void __launch_bounds__(256) zero_out_kernel(float4* __restrict__ out) {
    int i = blockIdx.x * 256 + threadIdx.x;
    out[i] = make_float4(0.f, 0.f, 0.f, 0.f);
}

__global__ void __launch_bounds__(256) scatter_add_kernel(
    const float4* __restrict__ upd4,
    const int4*  __restrict__ mask4,
    float* __restrict__ out)
{
    int i = blockIdx.x * 256 + threadIdx.x;       // float4 index
    int4   m = mask4[i];
    float4 u = upd4[i];
    // elem index = 4*i; batch = (4*i) >> 22; base = batch << 22
    int base = ((i << 2) >> BATCH_SHIFT) << BATCH_SHIFT;
    atomicAdd(out + (m.x + base), u.x);
    atomicAdd(out + (m.y + base), u.y);
    atomicAdd(out + (m.z + base), u.z);
    atomicAdd(out + (m.w + base), u.w);
}

extern "C" void kernel_launch(void* const* d_in, const int* in_sizes, int n_in,
                              void* d_out, int out_size) {
    const float* updates = (const float*)d_in[0];
    const int*   mask    = (const int*)d_in[1];
    float* out = (float*)d_out;

    // Zero the full output (poisoned before timing; stale between graph replays).
    int n4_out = N_OUT / 4;                       // 33,554,432 float4
    zero_out_kernel<<<n4_out / 256, 256>>>((float4*)out);

    // Scatter-add, 4 elements per thread.
    int n4_upd = N_UPD / 4;                       // 8,388,608 float4
    scatter_add_kernel<<<n4_upd / 256, 256>>>(
        (const float4*)updates, (const int4*)mask, out);
}